// round 2
// baseline (speedup 1.0000x reference)
#include <cuda_runtime.h>
#include <math.h>

// ---------------- problem constants ----------------
#define Bb 4
#define Tt 1024
#define Dd 1024
#define Hh 16
#define HKVv 4
#define HDd 64
#define DPFf 4096
#define DEXPp 2048
#define NEXPn 10
#define TOPKk 3
#define GATE_STRENGTH 0.001f

// ---------------- scratch (device globals; no allocs allowed) ----------------
__device__ float g_h [Bb*Tt*Dd];                 // normed activations (reused 3x)
__device__ float g_q [Bb*Tt*Dd];                 // q, later reused for attn output o
__device__ float g_k [Bb*Tt*HKVv*HDd];
__device__ float g_v [Bb*Tt*HKVv*HDd];
__device__ float g_s [Bb*Hh*Tt*Tt];              // attention scores/probs (256MB)
__device__ float g_x1[Bb*Tt*Dd];                 // residual after attention
__device__ float g_gb[Bb*Tt*DPFf];               // gate buffer (pf + moe, in-place silu*up)
__device__ float g_ub[Bb*Tt*DPFf];               // up buffer
__device__ int   g_topi[Bb*TOPKk];
__device__ float g_topw[Bb*TOPKk];

// ---------------- reductions ----------------
template<bool MAXRED>
__device__ __forceinline__ float block_reduce(float v) {
    __shared__ float sh[33];
    int lane = threadIdx.x & 31, w = threadIdx.x >> 5;
    #pragma unroll
    for (int o = 16; o; o >>= 1) {
        float t = __shfl_xor_sync(0xffffffffu, v, o);
        v = MAXRED ? fmaxf(v, t) : v + t;
    }
    if (lane == 0) sh[w] = v;
    __syncthreads();
    if (w == 0) {
        int nw = blockDim.x >> 5;
        v = (lane < nw) ? sh[lane] : (MAXRED ? -3.4e38f : 0.f);
        #pragma unroll
        for (int o = 16; o; o >>= 1) {
            float t = __shfl_xor_sync(0xffffffffu, v, o);
            v = MAXRED ? fmaxf(v, t) : v + t;
        }
        if (lane == 0) sh[32] = v;
    }
    __syncthreads();
    return sh[32];
}

// ---------------- rmsnorm ----------------
__global__ void rmsnorm_kernel(const float* __restrict__ x, const float* __restrict__ w,
                               float* __restrict__ o) {
    long long row = blockIdx.x;
    const float* xr = x + row * Dd;
    float s = 0.f;
    for (int i = threadIdx.x; i < Dd; i += blockDim.x) { float v = xr[i]; s += v * v; }
    s = block_reduce<false>(s);
    float inv = rsqrtf(s * (1.f / Dd) + 1e-6f);
    for (int i = threadIdx.x; i < Dd; i += blockDim.x)
        o[row * Dd + i] = xr[i] * inv * w[i];
}

// ---------------- softmax: one warp per row, 8 rows per block ----------------
__global__ void softmax_kernel(float* __restrict__ s) {
    int lane = threadIdx.x & 31;
    int wrp  = threadIdx.x >> 5;
    long long row = (long long)blockIdx.x * 8 + wrp;
    float* r = s + row * (long long)Tt;
    float m = -3.4e38f;
    // Tt/32 = 32 elements per lane
    float vals[32];
    #pragma unroll
    for (int i = 0; i < 32; i++) {
        vals[i] = r[lane + i * 32];
        m = fmaxf(m, vals[i]);
    }
    #pragma unroll
    for (int o = 16; o; o >>= 1) m = fmaxf(m, __shfl_xor_sync(0xffffffffu, m, o));
    float sum = 0.f;
    #pragma unroll
    for (int i = 0; i < 32; i++) {
        vals[i] = expf(vals[i] - m);
        sum += vals[i];
    }
    #pragma unroll
    for (int o = 16; o; o >>= 1) sum += __shfl_xor_sync(0xffffffffu, sum, o);
    float inv = 1.f / sum;
    #pragma unroll
    for (int i = 0; i < 32; i++) r[lane + i * 32] = vals[i] * inv;
}

// ---------------- silu(g)*u in place + tension = mean(hid^2) per row ----------------
__global__ void silu_tension_kernel(float* __restrict__ g, const float* __restrict__ u,
                                    float* __restrict__ tension) {
    long long base = (long long)blockIdx.x * DPFf;
    float s = 0.f;
    for (int i = threadIdx.x; i < DPFf; i += blockDim.x) {
        float gv = g[base + i], uv = u[base + i];
        float v = gv / (1.f + expf(-gv)) * uv;
        g[base + i] = v;
        s += v * v;
    }
    s = block_reduce<false>(s);
    if (threadIdx.x == 0) tension[blockIdx.x] = s * (1.f / DPFf);
}

// ---------------- silu(g)*u in place (MoE) ----------------
__global__ void silu_mul_kernel(float* __restrict__ g, const float* __restrict__ u, long long n) {
    long long i = (long long)blockIdx.x * blockDim.x + threadIdx.x;
    if (i < n) {
        float gv = g[i];
        g[i] = gv / (1.f + expf(-gv)) * u[i];
    }
}

// ---------------- router: logits -> softmax -> top3 -> renorm ----------------
__global__ void router_kernel(const float* __restrict__ cv, const float* __restrict__ rw,
                              const float* __restrict__ rb, int* __restrict__ topi,
                              float* __restrict__ topw) {
    int b = threadIdx.x;
    if (b >= Bb) return;
    float lg[NEXPn];
    float mx = -3.4e38f;
    #pragma unroll
    for (int e = 0; e < NEXPn; e++) {
        float s = rb[e];
        #pragma unroll
        for (int j = 0; j < NEXPn; j++) s += cv[b * NEXPn + j] * rw[e * NEXPn + j];
        lg[e] = s; mx = fmaxf(mx, s);
    }
    float sum = 0.f;
    #pragma unroll
    for (int e = 0; e < NEXPn; e++) { lg[e] = expf(lg[e] - mx); sum += lg[e]; }
    float inv = 1.f / sum;
    #pragma unroll
    for (int e = 0; e < NEXPn; e++) lg[e] *= inv;
    bool used[NEXPn];
    #pragma unroll
    for (int e = 0; e < NEXPn; e++) used[e] = false;
    float wv[TOPKk]; int idx[TOPKk]; float wsum = 0.f;
    for (int i = 0; i < TOPKk; i++) {
        int best = -1; float bv = -1.f;
        for (int e = 0; e < NEXPn; e++)
            if (!used[e] && lg[e] > bv) { bv = lg[e]; best = e; }
        used[best] = true; idx[i] = best; wv[i] = bv; wsum += bv;
    }
    for (int i = 0; i < TOPKk; i++) {
        topi[b * TOPKk + i] = idx[i];
        topw[b * TOPKk + i] = wv[i] / wsum;
    }
}

// ---------------- generic batched tiled SGEMM ----------------
// C = A @ B (or A @ B^T if TRANSB), with epilogues:
//  EPI 0: C = acc*alpha
//  EPI 1: causal mask: C = (col>row) ? -1e30 : acc*alpha   (M==N==T per batch)
//  EPI 2: C = acc + R1
//  EPI 3: C = acc + R1 + GATE_STRENGTH*R2
//  EPI 4: C += acc * scalePtr[bz*scaleStride]
// Batch index bz: bo=bz/batchDiv, bi=bz%batchDiv. Operand offsets:
//   off = Outer*bo + Inner*(bi/Div)
// Optional dynamic B selection: B += eStride * eidx[bz*eidxStride]
#define BM 128
#define BN 64
#define BK 16

template<int EPI, bool TRANSB>
__global__ __launch_bounds__(256) void gemm_kernel(
    const float* __restrict__ A, const float* __restrict__ B, float* __restrict__ C,
    int M, int N, int K, int lda, int ldb, int ldc,
    int batchDiv,
    long long aO, long long aI, int aDiv,
    long long bO, long long bI, int bDiv,
    long long cO, long long cI,
    const int* __restrict__ eidx, int eidxStride, long long eStride,
    float alpha,
    const float* __restrict__ R1, const float* __restrict__ R2,
    const float* __restrict__ scalePtr, int scaleStride)
{
    __shared__ float As[BK][BM];
    __shared__ float Bs[BK][BN];

    int bz = blockIdx.z;
    int bo = bz / batchDiv, bi = bz - bo * batchDiv;
    const float* Ap = A + aO * bo + aI * (bi / aDiv);
    const float* Bp = B + bO * bo + bI * (bi / bDiv);
    if (eidx) Bp += eStride * (long long)eidx[bz * eidxStride];
    float* Cp = C + cO * bo + cI * bi;

    int tid = threadIdx.x;
    int rowBase = blockIdx.y * BM;
    int colBase = blockIdx.x * BN;
    int ty = tid >> 4, tx = tid & 15;

    // fully-masked causal tile: constant fill, skip GEMM
    if (EPI == 1 && colBase > rowBase + BM - 1) {
        #pragma unroll
        for (int i = 0; i < 8; i++) {
            int row = rowBase + ty * 8 + i;
            #pragma unroll
            for (int j = 0; j < 4; j++) {
                int col = colBase + tx * 4 + j;
                Cp[(long long)row * ldc + col] = -1e30f;
            }
        }
        return;
    }

    int aRow   = tid >> 2;
    int aK4    = (tid & 3) << 2;
    int bRowNN = tid >> 4;
    int bN4    = (tid & 15) << 2;
    int bRowNT = tid >> 2;
    int bK4    = (tid & 3) << 2;

    float acc[8][4];
    #pragma unroll
    for (int i = 0; i < 8; i++)
        #pragma unroll
        for (int j = 0; j < 4; j++) acc[i][j] = 0.f;

    for (int k0 = 0; k0 < K; k0 += BK) {
        #pragma unroll
        for (int r = 0; r < 2; r++) {
            int m = aRow + r * 64;
            float4 va = *(const float4*)(Ap + (long long)(rowBase + m) * lda + k0 + aK4);
            As[aK4 + 0][m] = va.x; As[aK4 + 1][m] = va.y;
            As[aK4 + 2][m] = va.z; As[aK4 + 3][m] = va.w;
        }
        if (TRANSB) {
            float4 vb = *(const float4*)(Bp + (long long)(colBase + bRowNT) * ldb + k0 + bK4);
            Bs[bK4 + 0][bRowNT] = vb.x; Bs[bK4 + 1][bRowNT] = vb.y;
            Bs[bK4 + 2][bRowNT] = vb.z; Bs[bK4 + 3][bRowNT] = vb.w;
        } else {
            *(float4*)&Bs[bRowNN][bN4] =
                *(const float4*)(Bp + (long long)(k0 + bRowNN) * ldb + colBase + bN4);
        }
        __syncthreads();
        #pragma unroll
        for (int kk = 0; kk < BK; kk++) {
            float4 a0 = *(const float4*)&As[kk][ty * 8];
            float4 a1 = *(const float4*)&As[kk][ty * 8 + 4];
            float4 b0 = *(const float4*)&Bs[kk][tx * 4];
            float ar[8] = {a0.x, a0.y, a0.z, a0.w, a1.x, a1.y, a1.z, a1.w};
            float br[4] = {b0.x, b0.y, b0.z, b0.w};
            #pragma unroll
            for (int i = 0; i < 8; i++)
                #pragma unroll
                for (int j = 0; j < 4; j++)
                    acc[i][j] += ar[i] * br[j];
        }
        __syncthreads();
    }

    float scl = 1.f;
    if (EPI == 4) scl = scalePtr[bz * scaleStride];

    #pragma unroll
    for (int i = 0; i < 8; i++) {
        int row = rowBase + ty * 8 + i;
        #pragma unroll
        for (int j = 0; j < 4; j++) {
            int col = colBase + tx * 4 + j;
            long long idx = (long long)row * ldc + col;
            float v = acc[i][j] * alpha;
            if (EPI == 1)      { if (col > row) v = -1e30f; }
            else if (EPI == 2) { v += R1[idx]; }
            else if (EPI == 3) { v += R1[idx] + GATE_STRENGTH * R2[idx]; }
            else if (EPI == 4) { v = Cp[idx] + acc[i][j] * scl; }
            Cp[idx] = v;
        }
    }
}

// ---------------- orchestration ----------------
extern "C" void kernel_launch(void* const* d_in, const int* in_sizes, int n_in,
                              void* d_out, int out_size) {
    const float* x        = (const float*)d_in[0];
    const float* cs       = (const float*)d_in[1];
    const float* cv       = (const float*)d_in[2];
    const float* ln_attn  = (const float*)d_in[3];
    const float* wq       = (const float*)d_in[4];
    const float* wk       = (const float*)d_in[5];
    const float* wv       = (const float*)d_in[6];
    const float* wo       = (const float*)d_in[7];
    const float* ln_pf    = (const float*)d_in[8];
    const float* pf_gate  = (const float*)d_in[9];
    const float* pf_up    = (const float*)d_in[10];
    const float* pf_down  = (const float*)d_in[11];
    const float* ln_moe   = (const float*)d_in[12];
    const float* exp_gate = (const float*)d_in[13];
    const float* exp_up   = (const float*)d_in[14];
    const float* exp_down = (const float*)d_in[15];
    const float* router_w = (const float*)d_in[16];
    const float* router_b = (const float*)d_in[17];

    float* out     = (float*)d_out;
    float* tension = out + (long long)Bb * Tt * Dd;

    static float *h = nullptr, *q, *k, *v, *s, *x1, *gb, *ub, *topw;
    static int* topi;
    if (!h) {
        cudaGetSymbolAddress((void**)&h,    g_h);
        cudaGetSymbolAddress((void**)&q,    g_q);
        cudaGetSymbolAddress((void**)&k,    g_k);
        cudaGetSymbolAddress((void**)&v,    g_v);
        cudaGetSymbolAddress((void**)&s,    g_s);
        cudaGetSymbolAddress((void**)&x1,   g_x1);
        cudaGetSymbolAddress((void**)&gb,   g_gb);
        cudaGetSymbolAddress((void**)&ub,   g_ub);
        cudaGetSymbolAddress((void**)&topi, g_topi);
        cudaGetSymbolAddress((void**)&topw, g_topw);
    }

    const int BT = Bb * Tt;  // 4096

    // 1) h = rmsnorm(x, ln_attn)
    rmsnorm_kernel<<<BT, 256>>>(x, ln_attn, h);

    // 2) q/k/v projections
    gemm_kernel<0, false><<<dim3(Dd / BN, BT / BM, 1), 256>>>(
        h, wq, q, BT, Dd, Dd, Dd, Dd, Dd,
        1, 0, 0, 1, 0, 0, 1, 0, 0,
        nullptr, 0, 0, 1.f, nullptr, nullptr, nullptr, 0);
    gemm_kernel<0, false><<<dim3((HKVv * HDd) / BN, BT / BM, 1), 256>>>(
        h, wk, k, BT, HKVv * HDd, Dd, Dd, HKVv * HDd, HKVv * HDd,
        1, 0, 0, 1, 0, 0, 1, 0, 0,
        nullptr, 0, 0, 1.f, nullptr, nullptr, nullptr, 0);
    gemm_kernel<0, false><<<dim3((HKVv * HDd) / BN, BT / BM, 1), 256>>>(
        h, wv, v, BT, HKVv * HDd, Dd, Dd, HKVv * HDd, HKVv * HDd,
        1, 0, 0, 1, 0, 0, 1, 0, 0,
        nullptr, 0, 0, 1.f, nullptr, nullptr, nullptr, 0);

    // 3) scores = q @ k^T / 8, causal masked.  batch = B*H, bi = head
    gemm_kernel<1, true><<<dim3(Tt / BN, Tt / BM, Bb * Hh), 256>>>(
        q, k, s, Tt, Tt, HDd, Dd, HKVv * HDd, Tt,
        Hh,
        (long long)Tt * Dd, HDd, 1,
        (long long)Tt * HKVv * HDd, HDd, Hh / HKVv,
        (long long)Hh * Tt * Tt, (long long)Tt * Tt,
        nullptr, 0, 0, 0.125f, nullptr, nullptr, nullptr, 0);

    // 4) softmax rows (1 warp per row, 8 rows per block)
    softmax_kernel<<<Bb * Hh * Tt / 8, 256>>>(s);

    // 5) o = attn @ v  (into q buffer, layout (B,T,H,HD))
    gemm_kernel<0, false><<<dim3(HDd / BN, Tt / BM, Bb * Hh), 256>>>(
        s, v, q, Tt, HDd, Tt, Tt, HKVv * HDd, Dd,
        Hh,
        (long long)Hh * Tt * Tt, (long long)Tt * Tt, 1,
        (long long)Tt * HKVv * HDd, HDd, Hh / HKVv,
        (long long)Tt * Dd, HDd,
        nullptr, 0, 0, 1.f, nullptr, nullptr, nullptr, 0);

    // 6) x1 = o @ wo + x
    gemm_kernel<2, false><<<dim3(Dd / BN, BT / BM, 1), 256>>>(
        q, wo, x1, BT, Dd, Dd, Dd, Dd, Dd,
        1, 0, 0, 1, 0, 0, 1, 0, 0,
        nullptr, 0, 0, 1.f, x, nullptr, nullptr, 0);

    // 7) h = rmsnorm(x1, ln_pf)
    rmsnorm_kernel<<<BT, 256>>>(x1, ln_pf, h);

    // 8) pf gate/up
    gemm_kernel<0, false><<<dim3(DPFf / BN, BT / BM, 1), 256>>>(
        h, pf_gate, gb, BT, DPFf, Dd, Dd, DPFf, DPFf,
        1, 0, 0, 1, 0, 0, 1, 0, 0,
        nullptr, 0, 0, 1.f, nullptr, nullptr, nullptr, 0);
    gemm_kernel<0, false><<<dim3(DPFf / BN, BT / BM, 1), 256>>>(
        h, pf_up, ub, BT, DPFf, Dd, Dd, DPFf, DPFf,
        1, 0, 0, 1, 0, 0, 1, 0, 0,
        nullptr, 0, 0, 1.f, nullptr, nullptr, nullptr, 0);

    // 9) hid = silu(g)*u in place; tension = mean(hid^2)
    silu_tension_kernel<<<BT, 256>>>(gb, ub, tension);

    // 10) out(x2) = hid @ pf_down + x1 + 0.001*cs
    gemm_kernel<3, false><<<dim3(Dd / BN, BT / BM, 1), 256>>>(
        gb, pf_down, out, BT, Dd, DPFf, DPFf, Dd, Dd,
        1, 0, 0, 1, 0, 0, 1, 0, 0,
        nullptr, 0, 0, 1.f, x1, cs, nullptr, 0);

    // 11) h = rmsnorm(x2, ln_moe)
    rmsnorm_kernel<<<BT, 256>>>(out, ln_moe, h);

    // 12) router
    router_kernel<<<1, 32>>>(cv, router_w, router_b, topi, topw);

    // 13) MoE: 3 selected experts per batch
    for (int i = 0; i < TOPKk; i++) {
        gemm_kernel<0, false><<<dim3(DEXPp / BN, Tt / BM, Bb), 256>>>(
            h, exp_gate, gb, Tt, DEXPp, Dd, Dd, DEXPp, DEXPp,
            1,
            (long long)Tt * Dd, 0, 1,
            0, 0, 1,
            (long long)Tt * DEXPp, 0,
            topi + i, TOPKk, (long long)Dd * DEXPp,
            1.f, nullptr, nullptr, nullptr, 0);
        gemm_kernel<0, false><<<dim3(DEXPp / BN, Tt / BM, Bb), 256>>>(
            h, exp_up, ub, Tt, DEXPp, Dd, Dd, DEXPp, DEXPp,
            1,
            (long long)Tt * Dd, 0, 1,
            0, 0, 1,
            (long long)Tt * DEXPp, 0,
            topi + i, TOPKk, (long long)Dd * DEXPp,
            1.f, nullptr, nullptr, nullptr, 0);
        long long nact = (long long)Bb * Tt * DEXPp;
        silu_mul_kernel<<<(unsigned)((nact + 255) / 256), 256>>>(gb, ub, nact);
        gemm_kernel<4, false><<<dim3(Dd / BN, Tt / BM, Bb), 256>>>(
            gb, exp_down, out, Tt, Dd, DEXPp, DEXPp, Dd, Dd,
            1,
            (long long)Tt * DEXPp, 0, 1,
            0, 0, 1,
            (long long)Tt * Dd, 0,
            topi + i, TOPKk, (long long)DEXPp * Dd,
            1.f, nullptr, nullptr, topw + i, TOPKk);
    }
}

// round 5
// speedup vs baseline: 1.3396x; 1.3396x over previous
#include <cuda_runtime.h>
#include <math.h>
#include <stdint.h>

// ---------------- problem constants ----------------
#define Bb 4
#define Tt 1024
#define Dd 1024
#define Hh 16
#define HKVv 4
#define HDd 64
#define DPFf 4096
#define DEXPp 2048
#define NEXPn 10
#define TOPKk 3
#define GATE_STRENGTH 0.001f

// ---------------- scratch (device globals; no allocs allowed) ----------------
__device__ float g_h [Bb*Tt*Dd];
__device__ float g_q [Bb*Tt*Dd];
__device__ float g_k [Bb*Tt*HKVv*HDd];
__device__ float g_v [Bb*Tt*HKVv*HDd];
__device__ float g_s [Bb*Hh*Tt*Tt];              // attention scores/probs (256MB)
__device__ float g_x1[Bb*Tt*Dd];
__device__ float g_gb[Bb*Tt*DPFf];
__device__ float g_ub[Bb*Tt*DPFf];
__device__ int   g_topi[Bb*TOPKk];
__device__ float g_topw[Bb*TOPKk];

// ---------------- reductions ----------------
template<bool MAXRED>
__device__ __forceinline__ float block_reduce(float v) {
    __shared__ float sh[33];
    int lane = threadIdx.x & 31, w = threadIdx.x >> 5;
    #pragma unroll
    for (int o = 16; o; o >>= 1) {
        float t = __shfl_xor_sync(0xffffffffu, v, o);
        v = MAXRED ? fmaxf(v, t) : v + t;
    }
    if (lane == 0) sh[w] = v;
    __syncthreads();
    if (w == 0) {
        int nw = blockDim.x >> 5;
        v = (lane < nw) ? sh[lane] : (MAXRED ? -3.4e38f : 0.f);
        #pragma unroll
        for (int o = 16; o; o >>= 1) {
            float t = __shfl_xor_sync(0xffffffffu, v, o);
            v = MAXRED ? fmaxf(v, t) : v + t;
        }
        if (lane == 0) sh[32] = v;
    }
    __syncthreads();
    return sh[32];
}

// ---------------- rmsnorm ----------------
__global__ void rmsnorm_kernel(const float* __restrict__ x, const float* __restrict__ w,
                               float* __restrict__ o) {
    long long row = blockIdx.x;
    const float* xr = x + row * Dd;
    float s = 0.f;
    for (int i = threadIdx.x; i < Dd; i += blockDim.x) { float v = xr[i]; s += v * v; }
    s = block_reduce<false>(s);
    float inv = rsqrtf(s * (1.f / Dd) + 1e-6f);
    for (int i = threadIdx.x; i < Dd; i += blockDim.x)
        o[row * Dd + i] = xr[i] * inv * w[i];
}

// ---------------- softmax: one warp per row, 8 rows per block ----------------
__global__ void softmax_kernel(float* __restrict__ s) {
    int lane = threadIdx.x & 31;
    int wrp  = threadIdx.x >> 5;
    long long row = (long long)blockIdx.x * 8 + wrp;
    float* r = s + row * (long long)Tt;
    float m = -3.4e38f;
    float vals[32];
    #pragma unroll
    for (int i = 0; i < 32; i++) {
        vals[i] = r[lane + i * 32];
        m = fmaxf(m, vals[i]);
    }
    #pragma unroll
    for (int o = 16; o; o >>= 1) m = fmaxf(m, __shfl_xor_sync(0xffffffffu, m, o));
    float sum = 0.f;
    #pragma unroll
    for (int i = 0; i < 32; i++) {
        vals[i] = expf(vals[i] - m);
        sum += vals[i];
    }
    #pragma unroll
    for (int o = 16; o; o >>= 1) sum += __shfl_xor_sync(0xffffffffu, sum, o);
    float inv = 1.f / sum;
    #pragma unroll
    for (int i = 0; i < 32; i++) r[lane + i * 32] = vals[i] * inv;
}

// ---------------- silu(g)*u in place + tension ----------------
__global__ void silu_tension_kernel(float* __restrict__ g, const float* __restrict__ u,
                                    float* __restrict__ tension) {
    long long base = (long long)blockIdx.x * DPFf;
    float s = 0.f;
    for (int i = threadIdx.x; i < DPFf; i += blockDim.x) {
        float gv = g[base + i], uv = u[base + i];
        float v = gv / (1.f + expf(-gv)) * uv;
        g[base + i] = v;
        s += v * v;
    }
    s = block_reduce<false>(s);
    if (threadIdx.x == 0) tension[blockIdx.x] = s * (1.f / DPFf);
}

// ---------------- silu(g)*u in place (MoE) ----------------
__global__ void silu_mul_kernel(float* __restrict__ g, const float* __restrict__ u, long long n) {
    long long i = (long long)blockIdx.x * blockDim.x + threadIdx.x;
    if (i < n) {
        float gv = g[i];
        g[i] = gv / (1.f + expf(-gv)) * u[i];
    }
}

// ---------------- router ----------------
__global__ void router_kernel(const float* __restrict__ cv, const float* __restrict__ rw,
                              const float* __restrict__ rb, int* __restrict__ topi,
                              float* __restrict__ topw) {
    int b = threadIdx.x;
    if (b >= Bb) return;
    float lg[NEXPn];
    float mx = -3.4e38f;
    #pragma unroll
    for (int e = 0; e < NEXPn; e++) {
        float s = rb[e];
        #pragma unroll
        for (int j = 0; j < NEXPn; j++) s += cv[b * NEXPn + j] * rw[e * NEXPn + j];
        lg[e] = s; mx = fmaxf(mx, s);
    }
    float sum = 0.f;
    #pragma unroll
    for (int e = 0; e < NEXPn; e++) { lg[e] = expf(lg[e] - mx); sum += lg[e]; }
    float inv = 1.f / sum;
    #pragma unroll
    for (int e = 0; e < NEXPn; e++) lg[e] *= inv;
    bool used[NEXPn];
    #pragma unroll
    for (int e = 0; e < NEXPn; e++) used[e] = false;
    float wv[TOPKk]; int idx[TOPKk]; float wsum = 0.f;
    for (int i = 0; i < TOPKk; i++) {
        int best = -1; float bv = -1.f;
        for (int e = 0; e < NEXPn; e++)
            if (!used[e] && lg[e] > bv) { bv = lg[e]; best = e; }
        used[best] = true; idx[i] = best; wv[i] = bv; wsum += bv;
    }
    for (int i = 0; i < TOPKk; i++) {
        topi[b * TOPKk + i] = idx[i];
        topw[b * TOPKk + i] = wv[i] / wsum;
    }
}

// ---------------- TF32 tensor-core batched GEMM (single instantiation) ----------------
// C[M,N] = A[M,K] @ B (B row-major [K,N], or [N,K] if transB!=0), tf32 mma.
// Tile: 128x64x32. 256 threads, 8 warps as 4(M) x 2(N), warp tile 32x32.
// Smem in mma fragment order: As[((ks*8+mt)*32+lane)*4+reg], Bs[((ks*8+nt)*32+lane)*2+reg].
// Epilogues (runtime epi): 0 plain, 1 causal mask (+tile skip), 2 +R1,
// 3 +R1+GATE*R2, 4 C += acc*scale.

__device__ __forceinline__ uint32_t f2tf32(float x) {
    uint32_t u; asm("cvt.rna.tf32.f32 %0, %1;" : "=r"(u) : "f"(x)); return u;
}

__global__ __launch_bounds__(256) void gemm_kernel(
    const float* __restrict__ A, const float* __restrict__ B, float* __restrict__ C,
    int K, int lda, int ldb, int ldc,
    int epi, int transB,
    int batchDiv,
    long long aO, long long aI, int aDiv,
    long long bO, long long bI, int bDiv,
    long long cO, long long cI,
    const int* __restrict__ eidx, int eidxStride, long long eStride,
    float alpha,
    const float* __restrict__ R1, const float* __restrict__ R2,
    const float* __restrict__ scalePtr, int scaleStride)
{
    __shared__ uint32_t As[2][4096];   // 32 KB
    __shared__ uint32_t Bs[2][2048];   // 16 KB

    int bz = blockIdx.z;
    int bo = bz / batchDiv, bi = bz - bo * batchDiv;
    const float* Ap = A + aO * bo + aI * (bi / aDiv);
    const float* Bp = B + bO * bo + bI * (bi / bDiv);
    if (eidx) Bp += eStride * (long long)eidx[bz * eidxStride];
    float* Cp = C + cO * bo + cI * bi;

    int tid  = threadIdx.x;
    int lane = tid & 31;
    int w    = tid >> 5, wm = w >> 1, wn = w & 1;
    int rowBase = blockIdx.y * 128;
    int colBase = blockIdx.x * 64;

    // fully-masked causal tile: constant fill, skip GEMM
    if (epi == 1 && colBase > rowBase + 127) {
        for (int i = tid; i < 128 * 64; i += 256) {
            int r = i >> 6, c = i & 63;
            Cp[(long long)(rowBase + r) * ldc + colBase + c] = -1e30f;
        }
        return;
    }

    // ---- writer index precompute ----
    int aM[4], aK[4], aS[4];
    #pragma unroll
    for (int i = 0; i < 4; i++) {
        int f = tid + i * 256;              // 0..1023 over 128 rows x 8 float4
        int m = f >> 3, kq = f & 7;
        int ks = kq >> 1, c4 = (kq & 1) << 2;
        int mt = m >> 4, r = m & 15;
        int reg = (r >> 3) + ((c4 >> 2) << 1);
        aM[i] = m; aK[i] = kq << 2;
        aS[i] = ((ks * 8 + mt) * 32 + (r & 7) * 4) * 4 + reg;
    }
    int bNo[2], bKo[2], bS[2];
    const int bst = transB ? 2 : 8;         // uint32 stride between successive float4 elems
    if (transB) {
        #pragma unroll
        for (int i = 0; i < 2; i++) {
            int f = tid + i * 256;          // 0..511 over 64 n-rows x 8 float4
            int n = f >> 3, kq = f & 7;
            int ks = kq >> 1, reg = kq & 1;
            int nt = n >> 3, nr = n & 7;
            bNo[i] = n; bKo[i] = kq << 2;
            bS[i] = ((ks * 8 + nt) * 32 + nr * 4) * 2 + reg;
        }
    } else {
        #pragma unroll
        for (int i = 0; i < 2; i++) {
            int f = tid + i * 256;          // 0..511 over 32 k-rows x 16 float4
            int k = f >> 4, nq = f & 15;
            int ks = k >> 3, kc = k & 7;
            int reg = kc >> 2, kl = kc & 3;
            int nt = nq >> 1, nr0 = (nq & 1) << 2;
            bNo[i] = nq << 2; bKo[i] = k;
            bS[i] = ((ks * 8 + nt) * 32 + nr0 * 4 + kl) * 2 + reg;
        }
    }

    float acc[2][4][4];
    #pragma unroll
    for (int t = 0; t < 2; t++)
        #pragma unroll
        for (int u = 0; u < 4; u++)
            #pragma unroll
            for (int j = 0; j < 4; j++) acc[t][u][j] = 0.f;

    float4 ra[4], rb[2];

    // prologue load k0=0
    #pragma unroll
    for (int i = 0; i < 4; i++)
        ra[i] = *(const float4*)(Ap + (long long)(rowBase + aM[i]) * lda + aK[i]);
    #pragma unroll
    for (int i = 0; i < 2; i++)
        rb[i] = transB
            ? *(const float4*)(Bp + (long long)(colBase + bNo[i]) * ldb + bKo[i])
            : *(const float4*)(Bp + (long long)bKo[i] * ldb + colBase + bNo[i]);
    #pragma unroll
    for (int i = 0; i < 4; i++) {
        uint32_t* p = &As[0][aS[i]];
        p[0]  = f2tf32(ra[i].x); p[4]  = f2tf32(ra[i].y);
        p[8]  = f2tf32(ra[i].z); p[12] = f2tf32(ra[i].w);
    }
    #pragma unroll
    for (int i = 0; i < 2; i++) {
        uint32_t* p = &Bs[0][bS[i]];
        p[0]       = f2tf32(rb[i].x); p[bst]     = f2tf32(rb[i].y);
        p[2 * bst] = f2tf32(rb[i].z); p[3 * bst] = f2tf32(rb[i].w);
    }
    __syncthreads();

    int buf = 0;
    for (int k0 = 0; k0 < K; k0 += 32) {
        bool has_next = (k0 + 32) < K;
        if (has_next) {
            int kn = k0 + 32;
            #pragma unroll
            for (int i = 0; i < 4; i++)
                ra[i] = *(const float4*)(Ap + (long long)(rowBase + aM[i]) * lda + kn + aK[i]);
            #pragma unroll
            for (int i = 0; i < 2; i++)
                rb[i] = transB
                    ? *(const float4*)(Bp + (long long)(colBase + bNo[i]) * ldb + kn + bKo[i])
                    : *(const float4*)(Bp + (long long)(kn + bKo[i]) * ldb + colBase + bNo[i]);
        }
        // compute on buf
        #pragma unroll
        for (int ks = 0; ks < 4; ks++) {
            uint4 af[2]; uint2 bf[4];
            #pragma unroll
            for (int t = 0; t < 2; t++) {
                int mt = wm * 2 + t;
                af[t] = *(const uint4*)&As[buf][((ks * 8 + mt) * 32 + lane) * 4];
            }
            #pragma unroll
            for (int u = 0; u < 4; u++) {
                int nt = wn * 4 + u;
                bf[u] = *(const uint2*)&Bs[buf][((ks * 8 + nt) * 32 + lane) * 2];
            }
            #pragma unroll
            for (int t = 0; t < 2; t++)
                #pragma unroll
                for (int u = 0; u < 4; u++)
                    asm volatile(
                        "mma.sync.aligned.m16n8k8.row.col.f32.tf32.tf32.f32 "
                        "{%0,%1,%2,%3},{%4,%5,%6,%7},{%8,%9},{%0,%1,%2,%3};"
                        : "+f"(acc[t][u][0]), "+f"(acc[t][u][1]),
                          "+f"(acc[t][u][2]), "+f"(acc[t][u][3])
                        : "r"(af[t].x), "r"(af[t].y), "r"(af[t].z), "r"(af[t].w),
                          "r"(bf[u].x), "r"(bf[u].y));
        }
        if (has_next) {
            int nb = buf ^ 1;
            #pragma unroll
            for (int i = 0; i < 4; i++) {
                uint32_t* p = &As[nb][aS[i]];
                p[0]  = f2tf32(ra[i].x); p[4]  = f2tf32(ra[i].y);
                p[8]  = f2tf32(ra[i].z); p[12] = f2tf32(ra[i].w);
            }
            #pragma unroll
            for (int i = 0; i < 2; i++) {
                uint32_t* p = &Bs[nb][bS[i]];
                p[0]       = f2tf32(rb[i].x); p[bst]     = f2tf32(rb[i].y);
                p[2 * bst] = f2tf32(rb[i].z); p[3 * bst] = f2tf32(rb[i].w);
            }
            __syncthreads();
            buf = nb;
        }
    }

    // ---- epilogue ----
    float scl = (epi == 4) ? scalePtr[bz * scaleStride] : 1.f;
    #pragma unroll
    for (int t = 0; t < 2; t++) {
        int r0 = rowBase + wm * 32 + t * 16 + (lane >> 2);
        #pragma unroll
        for (int u = 0; u < 4; u++) {
            int c0 = colBase + wn * 32 + u * 8 + ((lane & 3) << 1);
            #pragma unroll
            for (int half = 0; half < 2; half++) {
                int row = r0 + half * 8;
                long long idx = (long long)row * ldc + c0;
                float v0 = acc[t][u][half * 2 + 0];
                float v1 = acc[t][u][half * 2 + 1];
                float o0 = v0 * alpha, o1 = v1 * alpha;
                if (epi == 1) {
                    if (c0 > row)     o0 = -1e30f;
                    if (c0 + 1 > row) o1 = -1e30f;
                } else if (epi == 2) {
                    o0 += R1[idx]; o1 += R1[idx + 1];
                } else if (epi == 3) {
                    o0 += R1[idx] + GATE_STRENGTH * R2[idx];
                    o1 += R1[idx + 1] + GATE_STRENGTH * R2[idx + 1];
                } else if (epi == 4) {
                    o0 = Cp[idx] + v0 * scl;
                    o1 = Cp[idx + 1] + v1 * scl;
                }
                *(float2*)&Cp[idx] = make_float2(o0, o1);
            }
        }
    }
}

// ---------------- orchestration ----------------
extern "C" void kernel_launch(void* const* d_in, const int* in_sizes, int n_in,
                              void* d_out, int out_size) {
    const float* x        = (const float*)d_in[0];
    const float* cs       = (const float*)d_in[1];
    const float* cv       = (const float*)d_in[2];
    const float* ln_attn  = (const float*)d_in[3];
    const float* wq       = (const float*)d_in[4];
    const float* wk       = (const float*)d_in[5];
    const float* wv       = (const float*)d_in[6];
    const float* wo       = (const float*)d_in[7];
    const float* ln_pf    = (const float*)d_in[8];
    const float* pf_gate  = (const float*)d_in[9];
    const float* pf_up    = (const float*)d_in[10];
    const float* pf_down  = (const float*)d_in[11];
    const float* ln_moe   = (const float*)d_in[12];
    const float* exp_gate = (const float*)d_in[13];
    const float* exp_up   = (const float*)d_in[14];
    const float* exp_down = (const float*)d_in[15];
    const float* router_w = (const float*)d_in[16];
    const float* router_b = (const float*)d_in[17];

    float* out     = (float*)d_out;
    float* tension = out + (long long)Bb * Tt * Dd;

    static float *h = nullptr, *q, *k, *v, *s, *x1, *gb, *ub, *topw;
    static int* topi;
    if (!h) {
        cudaGetSymbolAddress((void**)&h,    g_h);
        cudaGetSymbolAddress((void**)&q,    g_q);
        cudaGetSymbolAddress((void**)&k,    g_k);
        cudaGetSymbolAddress((void**)&v,    g_v);
        cudaGetSymbolAddress((void**)&s,    g_s);
        cudaGetSymbolAddress((void**)&x1,   g_x1);
        cudaGetSymbolAddress((void**)&gb,   g_gb);
        cudaGetSymbolAddress((void**)&ub,   g_ub);
        cudaGetSymbolAddress((void**)&topi, g_topi);
        cudaGetSymbolAddress((void**)&topw, g_topw);
    }

    const int BT = Bb * Tt;  // 4096
    const int BM = 128, BN = 64;

    // 1) h = rmsnorm(x, ln_attn)
    rmsnorm_kernel<<<BT, 256>>>(x, ln_attn, h);

    // 2) q/k/v projections
    gemm_kernel<<<dim3(Dd / BN, BT / BM, 1), 256>>>(
        h, wq, q, Dd, Dd, Dd, Dd, 0, 0,
        1, 0, 0, 1, 0, 0, 1, 0, 0,
        nullptr, 0, 0, 1.f, nullptr, nullptr, nullptr, 0);
    gemm_kernel<<<dim3((HKVv * HDd) / BN, BT / BM, 1), 256>>>(
        h, wk, k, Dd, Dd, HKVv * HDd, HKVv * HDd, 0, 0,
        1, 0, 0, 1, 0, 0, 1, 0, 0,
        nullptr, 0, 0, 1.f, nullptr, nullptr, nullptr, 0);
    gemm_kernel<<<dim3((HKVv * HDd) / BN, BT / BM, 1), 256>>>(
        h, wv, v, Dd, Dd, HKVv * HDd, HKVv * HDd, 0, 0,
        1, 0, 0, 1, 0, 0, 1, 0, 0,
        nullptr, 0, 0, 1.f, nullptr, nullptr, nullptr, 0);

    // 3) scores = q @ k^T / 8, causal masked.  batch = B*H, bi = head
    gemm_kernel<<<dim3(Tt / BN, Tt / BM, Bb * Hh), 256>>>(
        q, k, s, HDd, Dd, HKVv * HDd, Tt, 1, 1,
        Hh,
        (long long)Tt * Dd, HDd, 1,
        (long long)Tt * HKVv * HDd, HDd, Hh / HKVv,
        (long long)Hh * Tt * Tt, (long long)Tt * Tt,
        nullptr, 0, 0, 0.125f, nullptr, nullptr, nullptr, 0);

    // 4) softmax rows (1 warp per row, 8 rows per block)
    softmax_kernel<<<Bb * Hh * Tt / 8, 256>>>(s);

    // 5) o = attn @ v  (into q buffer, layout (B,T,H,HD))
    gemm_kernel<<<dim3(HDd / BN, Tt / BM, Bb * Hh), 256>>>(
        s, v, q, Tt, Tt, HKVv * HDd, Dd, 0, 0,
        Hh,
        (long long)Hh * Tt * Tt, (long long)Tt * Tt, 1,
        (long long)Tt * HKVv * HDd, HDd, Hh / HKVv,
        (long long)Tt * Dd, HDd,
        nullptr, 0, 0, 1.f, nullptr, nullptr, nullptr, 0);

    // 6) x1 = o @ wo + x
    gemm_kernel<<<dim3(Dd / BN, BT / BM, 1), 256>>>(
        q, wo, x1, Dd, Dd, Dd, Dd, 2, 0,
        1, 0, 0, 1, 0, 0, 1, 0, 0,
        nullptr, 0, 0, 1.f, x, nullptr, nullptr, 0);

    // 7) h = rmsnorm(x1, ln_pf)
    rmsnorm_kernel<<<BT, 256>>>(x1, ln_pf, h);

    // 8) pf gate/up
    gemm_kernel<<<dim3(DPFf / BN, BT / BM, 1), 256>>>(
        h, pf_gate, gb, Dd, Dd, DPFf, DPFf, 0, 0,
        1, 0, 0, 1, 0, 0, 1, 0, 0,
        nullptr, 0, 0, 1.f, nullptr, nullptr, nullptr, 0);
    gemm_kernel<<<dim3(DPFf / BN, BT / BM, 1), 256>>>(
        h, pf_up, ub, Dd, Dd, DPFf, DPFf, 0, 0,
        1, 0, 0, 1, 0, 0, 1, 0, 0,
        nullptr, 0, 0, 1.f, nullptr, nullptr, nullptr, 0);

    // 9) hid = silu(g)*u in place; tension = mean(hid^2)
    silu_tension_kernel<<<BT, 256>>>(gb, ub, tension);

    // 10) out(x2) = hid @ pf_down + x1 + 0.001*cs
    gemm_kernel<<<dim3(Dd / BN, BT / BM, 1), 256>>>(
        gb, pf_down, out, DPFf, DPFf, Dd, Dd, 3, 0,
        1, 0, 0, 1, 0, 0, 1, 0, 0,
        nullptr, 0, 0, 1.f, x1, cs, nullptr, 0);

    // 11) h = rmsnorm(x2, ln_moe)
    rmsnorm_kernel<<<BT, 256>>>(out, ln_moe, h);

    // 12) router
    router_kernel<<<1, 32>>>(cv, router_w, router_b, topi, topw);

    // 13) MoE: 3 selected experts per batch
    for (int i = 0; i < TOPKk; i++) {
        gemm_kernel<<<dim3(DEXPp / BN, Tt / BM, Bb), 256>>>(
            h, exp_gate, gb, Dd, Dd, DEXPp, DEXPp, 0, 0,
            1,
            (long long)Tt * Dd, 0, 1,
            0, 0, 1,
            (long long)Tt * DEXPp, 0,
            topi + i, TOPKk, (long long)Dd * DEXPp,
            1.f, nullptr, nullptr, nullptr, 0);
        gemm_kernel<<<dim3(DEXPp / BN, Tt / BM, Bb), 256>>>(
            h, exp_up, ub, Dd, Dd, DEXPp, DEXPp, 0, 0,
            1,
            (long long)Tt * Dd, 0, 1,
            0, 0, 1,
            (long long)Tt * DEXPp, 0,
            topi + i, TOPKk, (long long)Dd * DEXPp,
            1.f, nullptr, nullptr, nullptr, 0);
        long long nact = (long long)Bb * Tt * DEXPp;
        silu_mul_kernel<<<(unsigned)((nact + 255) / 256), 256>>>(gb, ub, nact);
        gemm_kernel<<<dim3(Dd / BN, Tt / BM, Bb), 256>>>(
            gb, exp_down, out, DEXPp, DEXPp, Dd, Dd, 4, 0,
            1,
            (long long)Tt * DEXPp, 0, 1,
            0, 0, 1,
            (long long)Tt * Dd, 0,
            topi + i, TOPKk, (long long)DEXPp * Dd,
            1.f, nullptr, nullptr, topw + i, TOPKk);
    }
}